// round 3
// baseline (speedup 1.0000x reference)
#include <cuda_runtime.h>
#include <cuda_fp16.h>
#include <mma.h>

using namespace nvcuda;

// Problem constants (from reference setup_inputs)
#define K_DIM 4096
#define N_DIM 11008
#define GROUP 128   // quant group size along K

// Tiling
#define BM 128
#define BN 128
#define BK 64
#define LDA 80      // (BK + 16) halves padded stride
#define LDB 80      // col-major B tile: element (k,n) at Bs[n*LDB + k]
#define NTHREADS 256

__global__ __launch_bounds__(NTHREADS)
void gptq_gemm_kernel(const float* __restrict__ x,
                      const int*   __restrict__ qw,
                      const float* __restrict__ scales,
                      const float* __restrict__ bias,
                      float*       __restrict__ out,
                      int M)
{
    __shared__ __align__(16) __half As[BM * LDA];   // 20480 B, row-major [m][k]
    __shared__ __align__(16) __half Bs[BN * LDB];   // 20480 B, col-major [n][k]

    const int tid     = threadIdx.x;
    const int warp_id = tid >> 5;
    const int lane    = tid & 31;

    const int m0 = blockIdx.y * BM;
    const int n0 = blockIdx.x * BN;

    // warp grid: 4 along M (32 rows each), 2 along N (64 cols each)
    const int wm = warp_id & 3;   // 0..3
    const int wn = warp_id >> 2;  // 0..1

    wmma::fragment<wmma::accumulator, 16, 16, 16, float> cf[2][4];
    #pragma unroll
    for (int i = 0; i < 2; i++)
        #pragma unroll
        for (int j = 0; j < 4; j++)
            wmma::fill_fragment(cf[i][j], 0.0f);

    // ---- register prefetch buffers ----
    // A: each thread handles 4 chunks of 8 floats (two float4 each)
    float4 a_reg[4][2];
    int    w_reg[4];
    float  s_reg[4];

    const int KT = K_DIM / BK;  // 64

    // A: i = tid + 256*r -> row = i/8 (0..127), col = (i%8)*8
    // B: i = tid + 256*r -> kq = i/128 (0..7), n = i%128

    auto load_tile = [&](int kt) {
        const int k0 = kt * BK;
        #pragma unroll
        for (int r = 0; r < 4; r++) {
            int i   = tid + NTHREADS * r;
            int row = i >> 3;
            int col = (i & 7) << 3;
            const float4* p = reinterpret_cast<const float4*>(
                x + (size_t)(m0 + row) * K_DIM + k0 + col);
            a_reg[r][0] = p[0];
            a_reg[r][1] = p[1];
        }
        const int g   = k0 >> 7;          // group index (BK=64 never crosses a 128 group)
        const int kq0 = k0 >> 3;          // packed row base
        #pragma unroll
        for (int r = 0; r < 4; r++) {
            int i  = tid + NTHREADS * r;
            int kq = i >> 7;
            int n  = i & 127;
            w_reg[r] = qw[(size_t)(kq0 + kq) * N_DIM + n0 + n];
            s_reg[r] = scales[(size_t)g * N_DIM + n0 + n];
        }
    };

    load_tile(0);

    for (int kt = 0; kt < KT; kt++) {
        // ---- store prefetched tile to smem (fp32->fp16 for A, dequant for B) ----
        #pragma unroll
        for (int r = 0; r < 4; r++) {
            int i   = tid + NTHREADS * r;
            int row = i >> 3;
            int col = (i & 7) << 3;
            __half2 h[4];
            h[0] = __floats2half2_rn(a_reg[r][0].x, a_reg[r][0].y);
            h[1] = __floats2half2_rn(a_reg[r][0].z, a_reg[r][0].w);
            h[2] = __floats2half2_rn(a_reg[r][1].x, a_reg[r][1].y);
            h[3] = __floats2half2_rn(a_reg[r][1].z, a_reg[r][1].w);
            *reinterpret_cast<uint4*>(&As[row * LDA + col]) =
                *reinterpret_cast<uint4*>(h);
        }
        #pragma unroll
        for (int r = 0; r < 4; r++) {
            int i  = tid + NTHREADS * r;
            int kq = i >> 7;
            int n  = i & 127;
            float sf = s_reg[r];
            unsigned int w = (unsigned int)w_reg[r];
            __half2 vals[4];
            #pragma unroll
            for (int j = 0; j < 4; j++) {
                int q0 = (int)((w >> (8 * j))     & 15) - 8;   // k offset 2j
                int q1 = (int)((w >> (8 * j + 4)) & 15) - 8;   // k offset 2j+1
                vals[j] = __floats2half2_rn((float)q0 * sf, (float)q1 * sf);
            }
            *reinterpret_cast<uint4*>(&Bs[n * LDB + kq * 8]) =
                *reinterpret_cast<uint4*>(vals);
        }
        __syncthreads();

        // ---- prefetch next tile while computing this one ----
        if (kt + 1 < KT) load_tile(kt + 1);

        // ---- tensor-core compute on smem tile ----
        wmma::fragment<wmma::matrix_a, 16, 16, 16, __half, wmma::row_major> af[2];
        wmma::fragment<wmma::matrix_b, 16, 16, 16, __half, wmma::col_major> bf[4];
        #pragma unroll
        for (int ks = 0; ks < BK / 16; ks++) {
            #pragma unroll
            for (int i = 0; i < 2; i++)
                wmma::load_matrix_sync(af[i], &As[(wm * 32 + i * 16) * LDA + ks * 16], LDA);
            #pragma unroll
            for (int j = 0; j < 4; j++)
                wmma::load_matrix_sync(bf[j], &Bs[(wn * 64 + j * 16) * LDB + ks * 16], LDB);
            #pragma unroll
            for (int i = 0; i < 2; i++)
                #pragma unroll
                for (int j = 0; j < 4; j++)
                    wmma::mma_sync(cf[i][j], af[i], bf[j], cf[i][j]);
        }
        __syncthreads();
    }

    // ---- epilogue: bias add + fp32 store ----
    // Reuse As as per-warp float staging (each warp owns 256 floats = 1KB).
    float* stage = reinterpret_cast<float*>(As) + warp_id * 256;

    #pragma unroll
    for (int i = 0; i < 2; i++) {
        #pragma unroll
        for (int j = 0; j < 4; j++) {
            wmma::store_matrix_sync(stage, cf[i][j], 16, wmma::mem_row_major);
            __syncwarp();
            const int row0 = m0 + wm * 32 + i * 16;
            const int col0 = n0 + wn * 64 + j * 16;
            #pragma unroll
            for (int e = lane; e < 256; e += 32) {
                int r = e >> 4;
                int c = e & 15;
                float v = stage[e] + bias[col0 + c];
                out[(size_t)(row0 + r) * N_DIM + col0 + c] = v;
            }
            __syncwarp();
        }
    }
}

extern "C" void kernel_launch(void* const* d_in, const int* in_sizes, int n_in,
                              void* d_out, int out_size)
{
    const float* x      = (const float*)d_in[0];
    const int*   qw     = (const int*)d_in[1];
    const float* scales = (const float*)d_in[2];
    const float* bias   = (const float*)d_in[3];
    float* out = (float*)d_out;

    const int M = in_sizes[0] / K_DIM;  // 8192

    dim3 grid(N_DIM / BN, M / BM);      // (86, 64)
    dim3 block(NTHREADS);
    gptq_gemm_kernel<<<grid, block>>>(x, qw, scales, bias, out, M);
}

// round 5
// speedup vs baseline: 2.8615x; 2.8615x over previous
#include <cuda_runtime.h>
#include <cuda_fp16.h>
#include <mma.h>
#include <cstdint>

using namespace nvcuda;

// ---------------- problem constants ----------------
#define K_DIM 4096
#define N_DIM 11008
#define M_DIM 8192

// ---------------- tiling ----------------
#define BM 128
#define BN 256
#define BK 64
#define KT (K_DIM / BK)      // 64
#define NTHREADS 256
#define LDT 72               // padded smem stride in halves (144B rows, conflict-free)

// smem byte offsets (dynamic)
#define A_BYTES (BM * LDT * 2)      // 18432
#define B_BYTES (BN * LDT * 2)      // 36864
#define OFF_A0 0
#define OFF_A1 (A_BYTES)
#define OFF_B0 (2 * A_BYTES)
#define OFF_B1 (2 * A_BYTES + B_BYTES)
#define SMEM_TOTAL (2 * A_BYTES + 2 * B_BYTES)   // 110592

// fp16 copy of x (fp32 inputs are exact fp16 values -> lossless)
__device__ __half g_xh[(size_t)M_DIM * K_DIM];

__device__ __forceinline__ uint32_t smem_u32(const void* p) {
    uint32_t a;
    asm("{ .reg .u64 t; cvta.to.shared.u64 t, %1; cvt.u32.u64 %0, t; }" : "=r"(a) : "l"(p));
    return a;
}
__device__ __forceinline__ void cp_async16(uint32_t dst, const void* src) {
    asm volatile("cp.async.ca.shared.global [%0], [%1], 16;" :: "r"(dst), "l"(src) : "memory");
}
__device__ __forceinline__ void cp_commit() {
    asm volatile("cp.async.commit_group;" ::: "memory");
}
__device__ __forceinline__ void cp_wait0() {
    asm volatile("cp.async.wait_group 0;" ::: "memory");
}

// ---------------- pre-pass: x fp32 -> fp16 scratch ----------------
__global__ __launch_bounds__(256) void convert_x_kernel(const float* __restrict__ x) {
    size_t i = (size_t)blockIdx.x * 256 + threadIdx.x;   // one uint4 (8 halves) per thread
    const float4* p = reinterpret_cast<const float4*>(x) + 2 * i;
    float4 a = p[0], b = p[1];
    __half2 h[4];
    h[0] = __floats2half2_rn(a.x, a.y);
    h[1] = __floats2half2_rn(a.z, a.w);
    h[2] = __floats2half2_rn(b.x, b.y);
    h[3] = __floats2half2_rn(b.z, b.w);
    reinterpret_cast<uint4*>(g_xh)[i] = *reinterpret_cast<uint4*>(h);
}

// ---------------- main fused dequant-GEMM ----------------
__global__ __launch_bounds__(NTHREADS, 1)
void gptq_gemm_kernel(const int*   __restrict__ qw,
                      const float* __restrict__ scales,
                      const float* __restrict__ bias,
                      float*       __restrict__ out)
{
    extern __shared__ __align__(128) char smem[];
    const uint32_t sb = smem_u32(smem);

    const int tid     = threadIdx.x;
    const int warp_id = tid >> 5;
    const int lane    = tid & 31;
    const int m0 = blockIdx.y * BM;
    const int n0 = blockIdx.x * BN;

    // warp grid: 2 along M x 4 along N, each warp owns 64x64
    const int wm = warp_id & 1;
    const int wn = warp_id >> 1;

    wmma::fragment<wmma::accumulator, 16, 16, 16, float> cf[4][4];
    #pragma unroll
    for (int i = 0; i < 4; i++)
        #pragma unroll
        for (int j = 0; j < 4; j++)
            wmma::fill_fragment(cf[i][j], 0.0f);

    // ---- B register prefetch state (one n-column per thread) ----
    int   wreg[8];
    float sreg;
    const int n = tid;  // 0..255

    auto ldgB = [&](int kt) {
        const int k0 = kt * BK;
        sreg = scales[(size_t)(k0 >> 7) * N_DIM + n0 + n];
        const int* qp = qw + (size_t)(k0 >> 3) * N_DIM + n0 + n;
        #pragma unroll
        for (int r = 0; r < 8; r++)
            wreg[r] = qp[(size_t)r * N_DIM];
    };

    auto cpA = [&](int kt, uint32_t a_off) {
        const int k0 = kt * BK;
        #pragma unroll
        for (int r = 0; r < 4; r++) {
            int idx = tid + NTHREADS * r;          // 0..1023
            int row = idx >> 3, c = idx & 7;
            cp_async16(sb + a_off + (uint32_t)(row * (LDT * 2) + c * 16),
                       g_xh + (size_t)(m0 + row) * K_DIM + k0 + c * 8);
        }
        cp_commit();
    };

    const __half2 c1032 = __floats2half2_rn(1032.0f, 1032.0f);

    // prologue
    cpA(0, OFF_A0);
    ldgB(0);

    for (int kt = 0; kt < KT; kt++) {
        const int buf = kt & 1;
        const uint32_t a_off = buf ? OFF_A1 : OFF_A0;
        const uint32_t b_off = buf ? OFF_B1 : OFF_B0;

        // ---- dequant B regs -> smem (this tile) ----
        {
            __half2 s2 = __half2half2(__float2half(sreg));
            #pragma unroll
            for (int r = 0; r < 8; r++) {
                unsigned w = (unsigned)wreg[r];
                __half2 v[4];
                #pragma unroll
                for (int j = 0; j < 4; j++) {
                    unsigned bj = (w >> (8 * j)) & 0xffu;
                    unsigned y  = ((bj | (bj << 12)) & 0x000f000fu) | 0x64006400u;
                    __half2 h2 = *reinterpret_cast<__half2*>(&y);   // (1024+q0, 1024+q1)
                    v[j] = __hmul2(__hsub2(h2, c1032), s2);          // exact (q-8)*s
                }
                *reinterpret_cast<uint4*>(smem + b_off + n * (LDT * 2) + r * 16) =
                    *reinterpret_cast<uint4*>(v);
            }
        }

        cp_wait0();          // A(kt) resident
        __syncthreads();     // tile (A,B)[buf] visible to all; prior compute on buf done

        // ---- prefetch next tile (overlaps with MMA below) ----
        if (kt + 1 < KT) {
            cpA(kt + 1, buf ? OFF_A0 : OFF_A1);
            ldgB(kt + 1);
        }

        // ---- tensor compute on smem[buf] ----
        const __half* As = reinterpret_cast<const __half*>(smem + a_off);
        const __half* Bs = reinterpret_cast<const __half*>(smem + b_off);
        #pragma unroll
        for (int ks = 0; ks < BK / 16; ks++) {
            wmma::fragment<wmma::matrix_a, 16, 16, 16, __half, wmma::row_major> af[4];
            wmma::fragment<wmma::matrix_b, 16, 16, 16, __half, wmma::col_major> bf[4];
            #pragma unroll
            for (int i = 0; i < 4; i++)
                wmma::load_matrix_sync(af[i], As + (wm * 64 + i * 16) * LDT + ks * 16, LDT);
            #pragma unroll
            for (int j = 0; j < 4; j++)
                wmma::load_matrix_sync(bf[j], Bs + (wn * 64 + j * 16) * LDT + ks * 16, LDT);
            #pragma unroll
            for (int i = 0; i < 4; i++)
                #pragma unroll
                for (int j = 0; j < 4; j++)
                    wmma::mma_sync(cf[i][j], af[i], bf[j], cf[i][j]);
        }
    }

    // ---- epilogue: strip-staged, coalesced, fused bias ----
    __syncthreads();   // everyone done with smem tiles; reuse as staging
    // per-warp stage: 16 rows x 64 cols floats, ldm=68 (4352 B each)
    float* stage = reinterpret_cast<float*>(smem) + warp_id * (17 * 64);

    const int row0 = m0 + wm * 64;
    const int col0 = n0 + wn * 64;

    #pragma unroll
    for (int i = 0; i < 4; i++) {
        #pragma unroll
        for (int j = 0; j < 4; j++)
            wmma::store_matrix_sync(stage + j * 16, cf[i][j], 68, wmma::mem_row_major);
        __syncwarp();
        #pragma unroll
        for (int q = 0; q < 8; q++) {
            int idx = q * 32 + lane;       // 0..255 float4s
            int r  = idx >> 4;
            int c4 = idx & 15;
            float4 v = *reinterpret_cast<const float4*>(stage + r * 68 + c4 * 4);
            const float4 bb = *reinterpret_cast<const float4*>(bias + col0 + c4 * 4);
            v.x += bb.x; v.y += bb.y; v.z += bb.z; v.w += bb.w;
            *reinterpret_cast<float4*>(
                out + (size_t)(row0 + i * 16 + r) * N_DIM + col0 + c4 * 4) = v;
        }
        __syncwarp();
    }
}

extern "C" void kernel_launch(void* const* d_in, const int* in_sizes, int n_in,
                              void* d_out, int out_size)
{
    const float* x      = (const float*)d_in[0];
    const int*   qw     = (const int*)d_in[1];
    const float* scales = (const float*)d_in[2];
    const float* bias   = (const float*)d_in[3];
    float* out = (float*)d_out;

    cudaFuncSetAttribute(gptq_gemm_kernel,
                         cudaFuncAttributeMaxDynamicSharedMemorySize, SMEM_TOTAL);

    // pre-pass: fp32 -> fp16 (8 halves per thread)
    convert_x_kernel<<<(M_DIM * K_DIM) / 8 / 256, 256>>>(x);

    dim3 grid(N_DIM / BN, M_DIM / BM);   // (43, 64)
    gptq_gemm_kernel<<<grid, NTHREADS, SMEM_TOTAL>>>(qw, scales, bias, out);
}

// round 6
// speedup vs baseline: 3.0730x; 1.0739x over previous
#include <cuda_runtime.h>
#include <cuda_fp16.h>
#include <mma.h>
#include <cstdint>

using namespace nvcuda;

// ---------------- problem constants ----------------
#define K_DIM 4096
#define N_DIM 11008
#define M_DIM 8192

// ---------------- tiling ----------------
#define BM 128
#define BN 128
#define BK 64
#define KT (K_DIM / BK)      // 64
#define NTHREADS 128         // 4 warps, 2x2 grid of 64x64 warp tiles
#define LDT 72               // padded smem stride in halves (144B rows)

// smem byte offsets (dynamic)
#define A_BYTES (BM * LDT * 2)      // 18432
#define B_BYTES (BN * LDT * 2)      // 18432
#define OFF_A0 0
#define OFF_A1 (A_BYTES)
#define OFF_B0 (2 * A_BYTES)
#define OFF_B1 (2 * A_BYTES + B_BYTES)
#define SMEM_TOTAL (2 * A_BYTES + 2 * B_BYTES)   // 73728 -> 2 CTAs/SM

// fp16 copy of x (fp32 inputs are exact fp16 values -> lossless)
__device__ __half g_xh[(size_t)M_DIM * K_DIM];

__device__ __forceinline__ uint32_t smem_u32(const void* p) {
    uint32_t a;
    asm("{ .reg .u64 t; cvta.to.shared.u64 t, %1; cvt.u32.u64 %0, t; }" : "=r"(a) : "l"(p));
    return a;
}
__device__ __forceinline__ void cp_async16(uint32_t dst, const void* src) {
    asm volatile("cp.async.cg.shared.global [%0], [%1], 16;" :: "r"(dst), "l"(src) : "memory");
}
__device__ __forceinline__ void cp_commit() {
    asm volatile("cp.async.commit_group;" ::: "memory");
}
__device__ __forceinline__ void cp_wait0() {
    asm volatile("cp.async.wait_group 0;" ::: "memory");
}

// ---------------- pre-pass: x fp32 -> fp16 scratch ----------------
__global__ __launch_bounds__(256) void convert_x_kernel(const float* __restrict__ x) {
    size_t i = (size_t)blockIdx.x * 256 + threadIdx.x;   // one uint4 (8 halves) per thread
    const float4* p = reinterpret_cast<const float4*>(x) + 2 * i;
    float4 a = p[0], b = p[1];
    __half2 h[4];
    h[0] = __floats2half2_rn(a.x, a.y);
    h[1] = __floats2half2_rn(a.z, a.w);
    h[2] = __floats2half2_rn(b.x, b.y);
    h[3] = __floats2half2_rn(b.z, b.w);
    reinterpret_cast<uint4*>(g_xh)[i] = *reinterpret_cast<uint4*>(h);
}

// ---------------- main fused dequant-GEMM ----------------
__global__ __launch_bounds__(NTHREADS, 2)
void gptq_gemm_kernel(const int*   __restrict__ qw,
                      const float* __restrict__ scales,
                      const float* __restrict__ bias,
                      float*       __restrict__ out)
{
    extern __shared__ __align__(128) char smem[];
    const uint32_t sb = smem_u32(smem);

    const int tid     = threadIdx.x;
    const int warp_id = tid >> 5;
    const int lane    = tid & 31;
    const int m0 = blockIdx.y * BM;
    const int n0 = blockIdx.x * BN;

    // warp grid: 2 along M x 2 along N, each warp owns 64x64
    const int wm = warp_id & 1;
    const int wn = warp_id >> 1;

    wmma::fragment<wmma::accumulator, 16, 16, 16, float> cf[4][4];
    #pragma unroll
    for (int i = 0; i < 4; i++)
        #pragma unroll
        for (int j = 0; j < 4; j++)
            wmma::fill_fragment(cf[i][j], 0.0f);

    // ---- B register prefetch state (one n-column per thread) ----
    int   wreg[8];
    float sreg;
    const int n = tid;  // 0..127

    auto ldgB = [&](int kt) {
        const int k0 = kt * BK;
        sreg = scales[(size_t)(k0 >> 7) * N_DIM + n0 + n];
        const int* qp = qw + (size_t)(k0 >> 3) * N_DIM + n0 + n;
        #pragma unroll
        for (int r = 0; r < 8; r++)
            wreg[r] = qp[(size_t)r * N_DIM];
    };

    auto cpA = [&](int kt, uint32_t a_off) {
        const int k0 = kt * BK;
        #pragma unroll
        for (int r = 0; r < 8; r++) {
            int idx = tid + NTHREADS * r;          // 0..1023
            int row = idx >> 3, c = idx & 7;
            cp_async16(sb + a_off + (uint32_t)(row * (LDT * 2) + c * 16),
                       g_xh + (size_t)(m0 + row) * K_DIM + k0 + c * 8);
        }
        cp_commit();
    };

    const __half2 c1032 = __floats2half2_rn(1032.0f, 1032.0f);

    // prologue
    cpA(0, OFF_A0);
    ldgB(0);

    for (int kt = 0; kt < KT; kt++) {
        const int buf = kt & 1;
        const uint32_t a_off = buf ? OFF_A1 : OFF_A0;
        const uint32_t b_off = buf ? OFF_B1 : OFF_B0;

        // ---- dequant B regs -> smem (this tile) ----
        {
            __half2 s2 = __half2half2(__float2half(sreg));
            #pragma unroll
            for (int r = 0; r < 8; r++) {
                unsigned w = (unsigned)wreg[r];
                __half2 v[4];
                #pragma unroll
                for (int j = 0; j < 4; j++) {
                    unsigned bj = (w >> (8 * j)) & 0xffu;
                    unsigned y  = ((bj | (bj << 12)) & 0x000f000fu) | 0x64006400u;
                    __half2 h2 = *reinterpret_cast<__half2*>(&y);   // (1024+q0, 1024+q1)
                    v[j] = __hmul2(__hsub2(h2, c1032), s2);          // exact (q-8)*s
                }
                *reinterpret_cast<uint4*>(smem + b_off + n * (LDT * 2) + r * 16) =
                    *reinterpret_cast<uint4*>(v);
            }
        }

        cp_wait0();          // A(kt) resident
        __syncthreads();     // tile (A,B)[buf] visible; prior compute on buf done

        // ---- prefetch next tile (overlaps with MMA below) ----
        if (kt + 1 < KT) {
            cpA(kt + 1, buf ? OFF_A0 : OFF_A1);
            ldgB(kt + 1);
        }

        // ---- tensor compute on smem[buf] ----
        const __half* As = reinterpret_cast<const __half*>(smem + a_off);
        const __half* Bs = reinterpret_cast<const __half*>(smem + b_off);
        #pragma unroll
        for (int ks = 0; ks < BK / 16; ks++) {
            wmma::fragment<wmma::matrix_a, 16, 16, 16, __half, wmma::row_major> af[4];
            wmma::fragment<wmma::matrix_b, 16, 16, 16, __half, wmma::col_major> bf[4];
            #pragma unroll
            for (int i = 0; i < 4; i++)
                wmma::load_matrix_sync(af[i], As + (wm * 64 + i * 16) * LDT + ks * 16, LDT);
            #pragma unroll
            for (int j = 0; j < 4; j++)
                wmma::load_matrix_sync(bf[j], Bs + (wn * 64 + j * 16) * LDT + ks * 16, LDT);
            #pragma unroll
            for (int i = 0; i < 4; i++)
                #pragma unroll
                for (int j = 0; j < 4; j++)
                    wmma::mma_sync(cf[i][j], af[i], bf[j], cf[i][j]);
        }
    }

    // ---- epilogue: strip-staged, coalesced, fused bias ----
    __syncthreads();   // everyone done with smem tiles; reuse as staging
    // per-warp stage: 16 rows x 64 cols floats, ldm=68 (4352 B each)
    float* stage = reinterpret_cast<float*>(smem) + warp_id * (17 * 64);

    const int row0 = m0 + wm * 64;
    const int col0 = n0 + wn * 64;

    #pragma unroll
    for (int i = 0; i < 4; i++) {
        #pragma unroll
        for (int j = 0; j < 4; j++)
            wmma::store_matrix_sync(stage + j * 16, cf[i][j], 68, wmma::mem_row_major);
        __syncwarp();
        #pragma unroll
        for (int q = 0; q < 8; q++) {
            int idx = q * 32 + lane;       // 0..255 float4s
            int r  = idx >> 4;
            int c4 = idx & 15;
            float4 v = *reinterpret_cast<const float4*>(stage + r * 68 + c4 * 4);
            const float4 bb = *reinterpret_cast<const float4*>(bias + col0 + c4 * 4);
            v.x += bb.x; v.y += bb.y; v.z += bb.z; v.w += bb.w;
            *reinterpret_cast<float4*>(
                out + (size_t)(row0 + i * 16 + r) * N_DIM + col0 + c4 * 4) = v;
        }
        __syncwarp();
    }
}

extern "C" void kernel_launch(void* const* d_in, const int* in_sizes, int n_in,
                              void* d_out, int out_size)
{
    const float* x      = (const float*)d_in[0];
    const int*   qw     = (const int*)d_in[1];
    const float* scales = (const float*)d_in[2];
    const float* bias   = (const float*)d_in[3];
    float* out = (float*)d_out;

    cudaFuncSetAttribute(gptq_gemm_kernel,
                         cudaFuncAttributeMaxDynamicSharedMemorySize, SMEM_TOTAL);

    // pre-pass: fp32 -> fp16 (8 halves per thread)
    convert_x_kernel<<<(M_DIM * K_DIM) / 8 / 256, 256>>>(x);

    dim3 grid(N_DIM / BN, M_DIM / BM);   // (86, 64)
    gptq_gemm_kernel<<<grid, NTHREADS, SMEM_TOTAL>>>(qw, scales, bias, out);
}